// round 1
// baseline (speedup 1.0000x reference)
#include <cuda_runtime.h>
#include <cuda_bf16.h>
#include <cstdint>

// ---------------------------------------------------------------------------
// TotalAttention (Swin window attention), fp32 baseline pipeline:
//   1) SGEMM: q   = x @ wq  + bq   -> g_qkv[:, 0:256]
//   2) SGEMM: kv  = x @ wkv + bkv  -> g_qkv[:, 256:768]
//   3) attention per (window b, head h): S = scale*q_h @ k_h^T + bias(rel);
//      softmax; O_h = S @ v_h -> g_ao
//   4) SGEMM: out = g_ao @ wp + bp -> d_out
// Shapes: B=4096 windows, N=64 tokens, DIM=256, HEADS=8, HEAD_DIM=32.
// ---------------------------------------------------------------------------

#define B_WIN   4096
#define N_TOK   64
#define DIM_C   256
#define HEADS   8
#define HDIM    32
#define M_ROWS  (B_WIN * N_TOK)        // 262144
#define QKV_LD  768
#define SCALE_F 0.17677669529663687f   // 32^-0.5

// Device scratch (allocation-free rule: use __device__ globals)
__device__ float g_qkv[(size_t)M_ROWS * QKV_LD];   // 805 MB
__device__ float g_ao [(size_t)M_ROWS * DIM_C];    // 268 MB

// ---------------------------------------------------------------------------
// SGEMM: C[m, coloff+n] = A[m,:K] @ W[:K, n] + bias[n]
// BM=128, BN=128, BK=8, 256 threads, 8x8 per-thread tile.
// Requirements: M % 128 == 0, Nw % 128 == 0, K % 8 == 0 (all hold here).
// grid.x = M/128 (row tiles), grid.y = Nw/128 (col tiles).
// ---------------------------------------------------------------------------
#define GBM 128
#define GBN 128
#define GBK 8

__global__ __launch_bounds__(256, 2)
void sgemm128(const float* __restrict__ A,
              const float* __restrict__ W,
              const float* __restrict__ bias,
              float* __restrict__ C,
              int K, int Nw, int ldc, int coloff)
{
    __shared__ float As[GBK][GBM];
    __shared__ float Bs[GBK][GBN];

    const int tid = threadIdx.x;
    const size_t m0 = (size_t)blockIdx.x * GBM;
    const int    n0 = blockIdx.y * GBN;

    // global-load mapping
    const int arow = tid >> 1;          // 0..127
    const int acol = (tid & 1) * 4;     // 0 or 4
    const int brow = tid >> 5;          // 0..7
    const int bcol = (tid & 31) * 4;    // 0..124

    // compute mapping: 16x16 thread grid, 8x8 outputs each
    const int ty = tid >> 4;
    const int tx = tid & 15;

    const float* Aptr = A + (m0 + (size_t)arow) * K + acol;
    const float* Wptr = W + (size_t)brow * Nw + n0 + bcol;

    float acc[8][8];
#pragma unroll
    for (int i = 0; i < 8; i++)
#pragma unroll
        for (int j = 0; j < 8; j++) acc[i][j] = 0.0f;

    float4 aReg = *(const float4*)(Aptr);
    float4 bReg = *(const float4*)(Wptr);

    const int nIter = K / GBK;
    for (int kt = 0; kt < nIter; ++kt) {
        // stage regs -> smem (A transposed to k-major)
        As[acol + 0][arow] = aReg.x;
        As[acol + 1][arow] = aReg.y;
        As[acol + 2][arow] = aReg.z;
        As[acol + 3][arow] = aReg.w;
        *(float4*)&Bs[brow][bcol] = bReg;
        __syncthreads();

        if (kt + 1 < nIter) {
            aReg = *(const float4*)(Aptr + (size_t)(kt + 1) * GBK);
            bReg = *(const float4*)(Wptr + (size_t)(kt + 1) * GBK * Nw);
        }

#pragma unroll
        for (int k = 0; k < GBK; ++k) {
            float a[8], b[8];
#pragma unroll
            for (int i = 0; i < 8; i++) a[i] = As[k][ty * 8 + i];
#pragma unroll
            for (int j = 0; j < 8; j++) b[j] = Bs[k][tx * 8 + j];
#pragma unroll
            for (int i = 0; i < 8; i++)
#pragma unroll
                for (int j = 0; j < 8; j++)
                    acc[i][j] = fmaf(a[i], b[j], acc[i][j]);
        }
        __syncthreads();
    }

    float bia[8];
#pragma unroll
    for (int j = 0; j < 8; j++) bia[j] = bias[n0 + tx * 8 + j];

#pragma unroll
    for (int i = 0; i < 8; i++) {
        size_t row = m0 + (size_t)(ty * 8 + i);
        float* cp = C + row * ldc + coloff + n0 + tx * 8;
        float4 v0 = make_float4(acc[i][0] + bia[0], acc[i][1] + bia[1],
                                acc[i][2] + bia[2], acc[i][3] + bia[3]);
        float4 v1 = make_float4(acc[i][4] + bia[4], acc[i][5] + bia[5],
                                acc[i][6] + bia[6], acc[i][7] + bia[7]);
        *(float4*)(cp)     = v0;
        *(float4*)(cp + 4) = v1;
    }
}

// ---------------------------------------------------------------------------
// Attention: one block per (window b, head h). 256 threads.
//   qs/ks/vs: [64][32] fp32 tiles (padded). S: [64][64] scores (padded).
// ---------------------------------------------------------------------------
__global__ __launch_bounds__(256, 4)
void attn_kernel(const float* __restrict__ qkv,
                 const float* __restrict__ rpb,      // [225][8]
                 const int*   __restrict__ relidx,   // [64][64]
                 float* __restrict__ ao)
{
    const int b = blockIdx.x;
    const int h = blockIdx.y;
    const int tid = threadIdx.x;

    __shared__ float qs[64][33];
    __shared__ float ks[64][33];
    __shared__ float vs[64][33];
    __shared__ float S [64][65];

    const size_t base = (size_t)b * N_TOK * QKV_LD;
    const int hoff = h * HDIM;

    // load q (scaled), k, v tiles: 512 float4 each, 2 per thread
#pragma unroll
    for (int i = tid; i < 64 * 8; i += 256) {
        const int row = i >> 3;
        const int c4  = (i & 7) * 4;
        const float* rp = qkv + base + (size_t)row * QKV_LD + hoff + c4;
        float4 q = *(const float4*)(rp);
        float4 k = *(const float4*)(rp + 256);
        float4 v = *(const float4*)(rp + 512);
        qs[row][c4 + 0] = q.x * SCALE_F;
        qs[row][c4 + 1] = q.y * SCALE_F;
        qs[row][c4 + 2] = q.z * SCALE_F;
        qs[row][c4 + 3] = q.w * SCALE_F;
        ks[row][c4 + 0] = k.x;  ks[row][c4 + 1] = k.y;
        ks[row][c4 + 2] = k.z;  ks[row][c4 + 3] = k.w;
        vs[row][c4 + 0] = v.x;  vs[row][c4 + 1] = v.y;
        vs[row][c4 + 2] = v.z;  vs[row][c4 + 3] = v.w;
    }
    __syncthreads();

    // S[n][m] = sum_d qs[n][d] * ks[m][d]  (4x4 per thread)
    {
        const int ng = tid >> 4;   // 0..15 -> rows ng*4..+3
        const int mg = tid & 15;   // cols mg*4..+3
        float sacc[4][4];
#pragma unroll
        for (int i = 0; i < 4; i++)
#pragma unroll
            for (int j = 0; j < 4; j++) sacc[i][j] = 0.0f;

#pragma unroll 8
        for (int d = 0; d < HDIM; d++) {
            float a[4], bb[4];
#pragma unroll
            for (int i = 0; i < 4; i++) a[i]  = qs[ng * 4 + i][d];
#pragma unroll
            for (int j = 0; j < 4; j++) bb[j] = ks[mg * 4 + j][d];
#pragma unroll
            for (int i = 0; i < 4; i++)
#pragma unroll
                for (int j = 0; j < 4; j++)
                    sacc[i][j] = fmaf(a[i], bb[j], sacc[i][j]);
        }
#pragma unroll
        for (int i = 0; i < 4; i++)
#pragma unroll
            for (int j = 0; j < 4; j++) {
                const int n = ng * 4 + i, m = mg * 4 + j;
                const int idx = relidx[n * 64 + m];
                S[n][m] = sacc[i][j] + rpb[idx * HEADS + h];
            }
    }
    __syncthreads();

    // softmax per row: 4 threads per row (16 elems each), shfl over quad
    {
        const int rn = tid >> 2;
        const int q4 = (tid & 3) * 16;
        float mx = -1e30f;
#pragma unroll
        for (int j = 0; j < 16; j++) mx = fmaxf(mx, S[rn][q4 + j]);
        mx = fmaxf(mx, __shfl_xor_sync(0xffffffffu, mx, 1));
        mx = fmaxf(mx, __shfl_xor_sync(0xffffffffu, mx, 2));
        float e[16], sum = 0.0f;
#pragma unroll
        for (int j = 0; j < 16; j++) {
            e[j] = __expf(S[rn][q4 + j] - mx);
            sum += e[j];
        }
        sum += __shfl_xor_sync(0xffffffffu, sum, 1);
        sum += __shfl_xor_sync(0xffffffffu, sum, 2);
        const float inv = __frcp_rn(sum);
#pragma unroll
        for (int j = 0; j < 16; j++) S[rn][q4 + j] = e[j] * inv;
    }
    __syncthreads();

    // O = S @ V : thread -> row on (tid>>2), cols dg*8..+7 (dg = tid&3)
    {
        const int on = tid >> 2;
        const int dg = (tid & 3) * 8;
        float o[8];
#pragma unroll
        for (int j = 0; j < 8; j++) o[j] = 0.0f;
#pragma unroll 8
        for (int m = 0; m < 64; m++) {
            const float s = S[on][m];
#pragma unroll
            for (int j = 0; j < 8; j++)
                o[j] = fmaf(s, vs[m][dg + j], o[j]);
        }
        float* op = ao + ((size_t)b * N_TOK + on) * DIM_C + hoff + dg;
        *(float4*)(op)     = make_float4(o[0], o[1], o[2], o[3]);
        *(float4*)(op + 4) = make_float4(o[4], o[5], o[6], o[7]);
    }
}

// ---------------------------------------------------------------------------
extern "C" void kernel_launch(void* const* d_in, const int* in_sizes, int n_in,
                              void* d_out, int out_size)
{
    const float* x      = (const float*)d_in[0];
    const float* wq     = (const float*)d_in[1];
    const float* bq     = (const float*)d_in[2];
    const float* wkv    = (const float*)d_in[3];
    const float* bkv    = (const float*)d_in[4];
    const float* wp     = (const float*)d_in[5];
    const float* bp     = (const float*)d_in[6];
    const float* rpb    = (const float*)d_in[7];
    const int*   relidx = (const int*)  d_in[8];
    float* out = (float*)d_out;

    float* qkv = nullptr;
    float* ao  = nullptr;
    cudaGetSymbolAddress((void**)&qkv, g_qkv);
    cudaGetSymbolAddress((void**)&ao,  g_ao);

    // 1) q = x @ wq + bq  -> qkv[:, 0:256]
    {
        dim3 grid(M_ROWS / GBM, DIM_C / GBN);
        sgemm128<<<grid, 256>>>(x, wq, bq, qkv, DIM_C, DIM_C, QKV_LD, 0);
    }
    // 2) kv = x @ wkv + bkv -> qkv[:, 256:768]
    {
        dim3 grid(M_ROWS / GBM, (2 * DIM_C) / GBN);
        sgemm128<<<grid, 256>>>(x, wkv, bkv, qkv, DIM_C, 2 * DIM_C, QKV_LD, DIM_C);
    }
    // 3) attention
    {
        dim3 grid(B_WIN, HEADS);
        attn_kernel<<<grid, 256>>>(qkv, rpb, relidx, ao);
    }
    // 4) out = ao @ wp + bp
    {
        dim3 grid(M_ROWS / GBM, DIM_C / GBN);
        sgemm128<<<grid, 256>>>(ao, wp, bp, out, DIM_C, DIM_C, DIM_C, 0);
    }
}

// round 3
// speedup vs baseline: 1.1979x; 1.1979x over previous
#include <cuda_runtime.h>
#include <cuda_bf16.h>
#include <cstdint>

// ---------------------------------------------------------------------------
// TotalAttention (Swin window attention):
//   0) pack wq|wkv -> g_wqkv [256x768], bq|bkv -> g_bqkv
//   1) 3xTF32 MMA GEMM: qkv = x @ wqkv + bqkv      -> g_qkv [262144 x 768]
//   2) attention per (window b, head h) (fp32)     -> g_ao  [262144 x 256]
//   3) 3xTF32 MMA GEMM: out = g_ao @ wp + bp       -> d_out
// 3xTF32: a = a_hi + a_res (both tf32-rounded); acc += ah*bh + ah*br + ar*bh.
// Shapes: B=4096 windows, N=64 tokens, DIM=256, HEADS=8, HEAD_DIM=32.
// ---------------------------------------------------------------------------

#define B_WIN   4096
#define N_TOK   64
#define DIM_C   256
#define HEADS   8
#define HDIM    32
#define M_ROWS  (B_WIN * N_TOK)        // 262144
#define QKV_LD  768
#define SCALE_F 0.17677669529663687f   // 32^-0.5

// Device scratch (allocation-free rule: __device__ globals)
__device__ float g_qkv[(size_t)M_ROWS * QKV_LD];   // 805 MB
__device__ float g_ao [(size_t)M_ROWS * DIM_C];    // 268 MB
__device__ float g_wqkv[DIM_C * QKV_LD];           // 786 KB
__device__ float g_bqkv[QKV_LD];

// ---------------------------------------------------------------------------
// helpers
// ---------------------------------------------------------------------------
__device__ __forceinline__ void cp_async16(void* smem_dst, const void* gsrc) {
    unsigned saddr = (unsigned)__cvta_generic_to_shared(smem_dst);
    asm volatile("cp.async.cg.shared.global [%0], [%1], 16;\n"
                 :: "r"(saddr), "l"(gsrc));
}

__device__ __forceinline__ void mma_tf32(float* c, const unsigned* a, const unsigned* b) {
    asm volatile(
        "mma.sync.aligned.m16n8k8.row.col.f32.tf32.tf32.f32 "
        "{%0,%1,%2,%3}, {%4,%5,%6,%7}, {%8,%9}, {%0,%1,%2,%3};\n"
        : "+f"(c[0]), "+f"(c[1]), "+f"(c[2]), "+f"(c[3])
        : "r"(a[0]), "r"(a[1]), "r"(a[2]), "r"(a[3]),
          "r"(b[0]), "r"(b[1]));
}

__device__ __forceinline__ unsigned f2tf32(float f) {
    unsigned r;
    asm("cvt.rna.tf32.f32 %0, %1;\n" : "=r"(r) : "f"(f));
    return r;
}

// split f into (hi, res) both tf32-rounded
__device__ __forceinline__ void tf32_split(float f, unsigned& hi, unsigned& res) {
    hi = f2tf32(f);
    res = f2tf32(f - __uint_as_float(hi));
}

// ---------------------------------------------------------------------------
// pack wq (256x256) and wkv (256x512) into g_wqkv (256x768); biases likewise
// ---------------------------------------------------------------------------
__global__ void pack_w(const float* __restrict__ wq, const float* __restrict__ bq,
                       const float* __restrict__ wkv, const float* __restrict__ bkv)
{
    int i = blockIdx.x * blockDim.x + threadIdx.x;
    if (i < DIM_C * QKV_LD) {
        int k = i / QKV_LD, n = i % QKV_LD;
        g_wqkv[i] = (n < DIM_C) ? wq[k * DIM_C + n] : wkv[k * 512 + (n - DIM_C)];
    }
    if (i < QKV_LD) g_bqkv[i] = (i < DIM_C) ? bq[i] : bkv[i - DIM_C];
}

// ---------------------------------------------------------------------------
// 3xTF32 tensor-core GEMM: C[m, n] = A[m,:K] @ W[:K, n] + bias[n]
// BM=128, BN=128, BK=32. 256 threads = 8 warps, warp tile 64(M) x 32(N).
// Double-buffered cp.async. Smem: A m-major pad 36, B n-major pad 132.
// Requires M%128==0, Nw%128==0, K%32==0.
// ---------------------------------------------------------------------------
#define AS_STRIDE 36
#define BS_STRIDE 132
#define AS_FLOATS (128 * AS_STRIDE)   // 4608
#define BS_FLOATS (32 * BS_STRIDE)    // 4224
#define GEMM_SMEM ((2 * AS_FLOATS + 2 * BS_FLOATS) * 4)  // 70656 bytes

__global__ __launch_bounds__(256, 2)
void gemm_tf32(const float* __restrict__ A, const float* __restrict__ W,
               const float* __restrict__ bias, float* __restrict__ C,
               int K, int Nw, int ldc)
{
    extern __shared__ float sm[];
    float* sAb[2] = { sm, sm + AS_FLOATS };
    float* sBb[2] = { sm + 2 * AS_FLOATS, sm + 2 * AS_FLOATS + BS_FLOATS };

    const int tid  = threadIdx.x;
    const int warp = tid >> 5, lane = tid & 31;
    const int wm = warp >> 2, wn = warp & 3;      // 2 x 4 warp grid
    const int g  = lane >> 2, t  = lane & 3;
    const size_t m0 = (size_t)blockIdx.x * 128;
    const int    n0 = blockIdx.y * 128;

    // cp.async per-thread mapping (4 x 16B each for A and B per tile)
    const int arow = tid >> 3, acol = (tid & 7) << 2;    // A: 128 x 32
    const int brow = tid >> 5, bcol = (tid & 31) << 2;   // B: 32 x 128

    const int nkt = K / 32;

    float acc[4][4][4];
#pragma unroll
    for (int mt = 0; mt < 4; mt++)
#pragma unroll
        for (int nt = 0; nt < 4; nt++)
#pragma unroll
            for (int r = 0; r < 4; r++) acc[mt][nt][r] = 0.0f;

    // issue tile 0
    {
        const float* Ag = A + (m0 + arow) * K + acol;
#pragma unroll
        for (int i = 0; i < 4; i++)
            cp_async16(&sAb[0][(arow + 32 * i) * AS_STRIDE + acol],
                       Ag + (size_t)32 * i * K);
        const float* Wg = W + (size_t)brow * Nw + n0 + bcol;
#pragma unroll
        for (int i = 0; i < 4; i++)
            cp_async16(&sBb[0][(brow + 8 * i) * BS_STRIDE + bcol],
                       Wg + (size_t)8 * i * Nw);
        asm volatile("cp.async.commit_group;\n");
    }

    for (int kt = 0; kt < nkt; ++kt) {
        asm volatile("cp.async.wait_group 0;\n");
        __syncthreads();

        if (kt + 1 < nkt) {
            const int nb = (kt + 1) & 1;
            const float* Ag = A + (m0 + arow) * K + (kt + 1) * 32 + acol;
#pragma unroll
            for (int i = 0; i < 4; i++)
                cp_async16(&sAb[nb][(arow + 32 * i) * AS_STRIDE + acol],
                           Ag + (size_t)32 * i * K);
            const float* Wg = W + (size_t)((kt + 1) * 32 + brow) * Nw + n0 + bcol;
#pragma unroll
            for (int i = 0; i < 4; i++)
                cp_async16(&sBb[nb][(brow + 8 * i) * BS_STRIDE + bcol],
                           Wg + (size_t)8 * i * Nw);
            asm volatile("cp.async.commit_group;\n");
        }

        const float* As = sAb[kt & 1];
        const float* Bs = sBb[kt & 1];

#pragma unroll
        for (int ks = 0; ks < 4; ++ks) {
            const int ck = ks * 8;
            // B fragments for all 4 nt tiles, split hi/res (16 regs)
            unsigned bh[4][2], br[4][2];
#pragma unroll
            for (int nt = 0; nt < 4; nt++) {
                const int c0 = wn * 32 + nt * 8 + g;
                const float* p = Bs + (ck + t) * BS_STRIDE + c0;
                tf32_split(p[0],             bh[nt][0], br[nt][0]);  // (t,   g)
                tf32_split(p[4 * BS_STRIDE], bh[nt][1], br[nt][1]);  // (t+4, g)
            }
            // A fragments per mt (8 regs live), 3 MMAs per (mt, nt)
#pragma unroll
            for (int mt = 0; mt < 4; mt++) {
                const int r0 = wm * 64 + mt * 16 + g;
                const float* p = As + r0 * AS_STRIDE + ck + t;
                unsigned ah[4], ar[4];
                tf32_split(p[0],                 ah[0], ar[0]); // (g,   t)
                tf32_split(p[8 * AS_STRIDE],     ah[1], ar[1]); // (g+8, t)
                tf32_split(p[4],                 ah[2], ar[2]); // (g,   t+4)
                tf32_split(p[8 * AS_STRIDE + 4], ah[3], ar[3]); // (g+8, t+4)
#pragma unroll
                for (int nt = 0; nt < 4; nt++) {
                    mma_tf32(acc[mt][nt], ar, bh[nt]);   // res*hi
                    mma_tf32(acc[mt][nt], ah, br[nt]);   // hi*res
                    mma_tf32(acc[mt][nt], ah, bh[nt]);   // hi*hi
                }
            }
        }
        __syncthreads();
    }

    // epilogue: C layout c0/c1 -> (g, 2t..2t+1), c2/c3 -> (g+8, 2t..2t+1)
#pragma unroll
    for (int mt = 0; mt < 4; mt++) {
        const size_t r0 = m0 + wm * 64 + mt * 16 + g;
#pragma unroll
        for (int nt = 0; nt < 4; nt++) {
            const int col = n0 + wn * 32 + nt * 8 + 2 * t;
            const float b0 = bias[col], b1 = bias[col + 1];
            float* cp0 = C + r0 * ldc + col;
            float* cp1 = C + (r0 + 8) * ldc + col;
            *(float2*)cp0 = make_float2(acc[mt][nt][0] + b0, acc[mt][nt][1] + b1);
            *(float2*)cp1 = make_float2(acc[mt][nt][2] + b0, acc[mt][nt][3] + b1);
        }
    }
}

// ---------------------------------------------------------------------------
// Attention: one block per (window b, head h). 256 threads. (unchanged)
// ---------------------------------------------------------------------------
__global__ __launch_bounds__(256, 4)
void attn_kernel(const float* __restrict__ qkv,
                 const float* __restrict__ rpb,      // [225][8]
                 const int*   __restrict__ relidx,   // [64][64]
                 float* __restrict__ ao)
{
    const int b = blockIdx.x;
    const int h = blockIdx.y;
    const int tid = threadIdx.x;

    __shared__ float qs[64][33];
    __shared__ float ks[64][33];
    __shared__ float vs[64][33];
    __shared__ float S [64][65];

    const size_t base = (size_t)b * N_TOK * QKV_LD;
    const int hoff = h * HDIM;

#pragma unroll
    for (int i = tid; i < 64 * 8; i += 256) {
        const int row = i >> 3;
        const int c4  = (i & 7) * 4;
        const float* rp = qkv + base + (size_t)row * QKV_LD + hoff + c4;
        float4 q = *(const float4*)(rp);
        float4 k = *(const float4*)(rp + 256);
        float4 v = *(const float4*)(rp + 512);
        qs[row][c4 + 0] = q.x * SCALE_F;
        qs[row][c4 + 1] = q.y * SCALE_F;
        qs[row][c4 + 2] = q.z * SCALE_F;
        qs[row][c4 + 3] = q.w * SCALE_F;
        ks[row][c4 + 0] = k.x;  ks[row][c4 + 1] = k.y;
        ks[row][c4 + 2] = k.z;  ks[row][c4 + 3] = k.w;
        vs[row][c4 + 0] = v.x;  vs[row][c4 + 1] = v.y;
        vs[row][c4 + 2] = v.z;  vs[row][c4 + 3] = v.w;
    }
    __syncthreads();

    {
        const int ng = tid >> 4;
        const int mg = tid & 15;
        float sacc[4][4];
#pragma unroll
        for (int i = 0; i < 4; i++)
#pragma unroll
            for (int j = 0; j < 4; j++) sacc[i][j] = 0.0f;

#pragma unroll 8
        for (int d = 0; d < HDIM; d++) {
            float a[4], bb[4];
#pragma unroll
            for (int i = 0; i < 4; i++) a[i]  = qs[ng * 4 + i][d];
#pragma unroll
            for (int j = 0; j < 4; j++) bb[j] = ks[mg * 4 + j][d];
#pragma unroll
            for (int i = 0; i < 4; i++)
#pragma unroll
                for (int j = 0; j < 4; j++)
                    sacc[i][j] = fmaf(a[i], bb[j], sacc[i][j]);
        }
#pragma unroll
        for (int i = 0; i < 4; i++)
#pragma unroll
            for (int j = 0; j < 4; j++) {
                const int n = ng * 4 + i, m = mg * 4 + j;
                const int idx = relidx[n * 64 + m];
                S[n][m] = sacc[i][j] + rpb[idx * HEADS + h];
            }
    }
    __syncthreads();

    {
        const int rn = tid >> 2;
        const int q4 = (tid & 3) * 16;
        float mx = -1e30f;
#pragma unroll
        for (int j = 0; j < 16; j++) mx = fmaxf(mx, S[rn][q4 + j]);
        mx = fmaxf(mx, __shfl_xor_sync(0xffffffffu, mx, 1));
        mx = fmaxf(mx, __shfl_xor_sync(0xffffffffu, mx, 2));
        float e[16], sum = 0.0f;
#pragma unroll
        for (int j = 0; j < 16; j++) {
            e[j] = __expf(S[rn][q4 + j] - mx);
            sum += e[j];
        }
        sum += __shfl_xor_sync(0xffffffffu, sum, 1);
        sum += __shfl_xor_sync(0xffffffffu, sum, 2);
        const float inv = __frcp_rn(sum);
#pragma unroll
        for (int j = 0; j < 16; j++) S[rn][q4 + j] = e[j] * inv;
    }
    __syncthreads();

    {
        const int on = tid >> 2;
        const int dg = (tid & 3) * 8;
        float o[8];
#pragma unroll
        for (int j = 0; j < 8; j++) o[j] = 0.0f;
#pragma unroll 8
        for (int m = 0; m < 64; m++) {
            const float s = S[on][m];
#pragma unroll
            for (int j = 0; j < 8; j++)
                o[j] = fmaf(s, vs[m][dg + j], o[j]);
        }
        float* op = ao + ((size_t)b * N_TOK + on) * DIM_C + hoff + dg;
        *(float4*)(op)     = make_float4(o[0], o[1], o[2], o[3]);
        *(float4*)(op + 4) = make_float4(o[4], o[5], o[6], o[7]);
    }
}

// ---------------------------------------------------------------------------
extern "C" void kernel_launch(void* const* d_in, const int* in_sizes, int n_in,
                              void* d_out, int out_size)
{
    const float* x      = (const float*)d_in[0];
    const float* wq     = (const float*)d_in[1];
    const float* bq     = (const float*)d_in[2];
    const float* wkv    = (const float*)d_in[3];
    const float* bkv    = (const float*)d_in[4];
    const float* wp     = (const float*)d_in[5];
    const float* bp     = (const float*)d_in[6];
    const float* rpb    = (const float*)d_in[7];
    const int*   relidx = (const int*)  d_in[8];
    float* out = (float*)d_out;

    float* qkv = nullptr;
    float* ao  = nullptr;
    float* wqkv = nullptr;
    float* bqkv = nullptr;
    cudaGetSymbolAddress((void**)&qkv,  g_qkv);
    cudaGetSymbolAddress((void**)&ao,   g_ao);
    cudaGetSymbolAddress((void**)&wqkv, g_wqkv);
    cudaGetSymbolAddress((void**)&bqkv, g_bqkv);

    cudaFuncSetAttribute(gemm_tf32, cudaFuncAttributeMaxDynamicSharedMemorySize,
                         GEMM_SMEM);

    // 0) pack fused qkv weights
    pack_w<<<(DIM_C * QKV_LD + 255) / 256, 256>>>(wq, bq, wkv, bkv);

    // 1) qkv = x @ wqkv + bqkv
    {
        dim3 grid(M_ROWS / 128, QKV_LD / 128);   // 2048 x 6
        gemm_tf32<<<grid, 256, GEMM_SMEM>>>(x, wqkv, bqkv, qkv, DIM_C, QKV_LD, QKV_LD);
    }
    // 2) attention
    {
        dim3 grid(B_WIN, HEADS);
        attn_kernel<<<grid, 256>>>(qkv, rpb, relidx, ao);
    }
    // 3) out = ao @ wp + bp
    {
        dim3 grid(M_ROWS / 128, DIM_C / 128);    // 2048 x 2
        gemm_tf32<<<grid, 256, GEMM_SMEM>>>(ao, wp, bp, out, DIM_C, DIM_C, DIM_C);
    }
}

// round 4
// speedup vs baseline: 1.6654x; 1.3903x over previous
#include <cuda_runtime.h>
#include <cuda_bf16.h>
#include <cstdint>

// ---------------------------------------------------------------------------
// TotalAttention (Swin window attention):
//   0) pack wq|wkv -> g_wqkv; biases; bias table g_bias[h][n][m]
//   1) 3xTF32 MMA GEMM: qkv = x @ wqkv + bqkv      -> g_qkv [262144 x 768]
//   2) tensor-core attention (warp = head)         -> g_ao  [262144 x 256]
//   3) 3xTF32 MMA GEMM: out = g_ao @ wp + bp       -> d_out
// 3xTF32 split: hi = f & 0xFFFFE000 (LOP3), res = f - hi (FADD); hardware
// truncates res's low mantissa bits inside the MMA (error ~2^-21).
// ---------------------------------------------------------------------------

#define B_WIN   4096
#define N_TOK   64
#define DIM_C   256
#define HEADS   8
#define HDIM    32
#define M_ROWS  (B_WIN * N_TOK)        // 262144
#define QKV_LD  768
#define SCALE_F 0.17677669529663687f   // 32^-0.5

__device__ float g_qkv[(size_t)M_ROWS * QKV_LD];   // 805 MB
__device__ float g_ao [(size_t)M_ROWS * DIM_C];    // 268 MB
__device__ float g_wqkv[DIM_C * QKV_LD];
__device__ float g_bqkv[QKV_LD];
__device__ float g_bias[HEADS * N_TOK * N_TOK];    // [h][n][m] 131 KB

// ---------------------------------------------------------------------------
__device__ __forceinline__ void cp_async16(void* smem_dst, const void* gsrc) {
    unsigned saddr = (unsigned)__cvta_generic_to_shared(smem_dst);
    asm volatile("cp.async.cg.shared.global [%0], [%1], 16;\n"
                 :: "r"(saddr), "l"(gsrc));
}

__device__ __forceinline__ void mma_tf32(float* c, const unsigned* a, const unsigned* b) {
    asm volatile(
        "mma.sync.aligned.m16n8k8.row.col.f32.tf32.tf32.f32 "
        "{%0,%1,%2,%3}, {%4,%5,%6,%7}, {%8,%9}, {%0,%1,%2,%3};\n"
        : "+f"(c[0]), "+f"(c[1]), "+f"(c[2]), "+f"(c[3])
        : "r"(a[0]), "r"(a[1]), "r"(a[2]), "r"(a[3]),
          "r"(b[0]), "r"(b[1]));
}

// cheap split: hi = truncate-to-tf32 (LOP3); res = f - hi (FADD, raw bits —
// HW mma truncates res's low bits, error ~2^-21 of |f|)
__device__ __forceinline__ void tf32_split(float f, unsigned& hi, unsigned& res) {
    hi  = __float_as_uint(f) & 0xFFFFE000u;
    res = __float_as_uint(f - __uint_as_float(hi));
}

// ---------------------------------------------------------------------------
// pack: fused qkv weights/bias + precomputed rel-pos bias table
// ---------------------------------------------------------------------------
__global__ void pack_w(const float* __restrict__ wq, const float* __restrict__ bq,
                       const float* __restrict__ wkv, const float* __restrict__ bkv,
                       const float* __restrict__ rpb, const int* __restrict__ relidx)
{
    int i = blockIdx.x * blockDim.x + threadIdx.x;
    if (i < DIM_C * QKV_LD) {
        int k = i / QKV_LD, n = i % QKV_LD;
        g_wqkv[i] = (n < DIM_C) ? wq[k * DIM_C + n] : wkv[k * 512 + (n - DIM_C)];
    }
    if (i < QKV_LD) g_bqkv[i] = (i < DIM_C) ? bq[i] : bkv[i - DIM_C];
    if (i < HEADS * N_TOK * N_TOK) {
        int h = i >> 12, nm = i & 4095;
        g_bias[i] = rpb[relidx[nm] * HEADS + h];
    }
}

// ---------------------------------------------------------------------------
// 3xTF32 tensor-core GEMM (same structure as round 3, cheaper split)
// ---------------------------------------------------------------------------
#define AS_STRIDE 36
#define BS_STRIDE 132
#define AS_FLOATS (128 * AS_STRIDE)
#define BS_FLOATS (32 * BS_STRIDE)
#define GEMM_SMEM ((2 * AS_FLOATS + 2 * BS_FLOATS) * 4)

__global__ __launch_bounds__(256, 2)
void gemm_tf32(const float* __restrict__ A, const float* __restrict__ W,
               const float* __restrict__ bias, float* __restrict__ C,
               int K, int Nw, int ldc)
{
    extern __shared__ float sm[];
    float* sAb[2] = { sm, sm + AS_FLOATS };
    float* sBb[2] = { sm + 2 * AS_FLOATS, sm + 2 * AS_FLOATS + BS_FLOATS };

    const int tid  = threadIdx.x;
    const int warp = tid >> 5, lane = tid & 31;
    const int wm = warp >> 2, wn = warp & 3;
    const int g  = lane >> 2, t  = lane & 3;
    const size_t m0 = (size_t)blockIdx.x * 128;
    const int    n0 = blockIdx.y * 128;

    const int arow = tid >> 3, acol = (tid & 7) << 2;
    const int brow = tid >> 5, bcol = (tid & 31) << 2;

    const int nkt = K / 32;

    float acc[4][4][4];
#pragma unroll
    for (int mt = 0; mt < 4; mt++)
#pragma unroll
        for (int nt = 0; nt < 4; nt++)
#pragma unroll
            for (int r = 0; r < 4; r++) acc[mt][nt][r] = 0.0f;

    {
        const float* Ag = A + (m0 + arow) * K + acol;
#pragma unroll
        for (int i = 0; i < 4; i++)
            cp_async16(&sAb[0][(arow + 32 * i) * AS_STRIDE + acol],
                       Ag + (size_t)32 * i * K);
        const float* Wg = W + (size_t)brow * Nw + n0 + bcol;
#pragma unroll
        for (int i = 0; i < 4; i++)
            cp_async16(&sBb[0][(brow + 8 * i) * BS_STRIDE + bcol],
                       Wg + (size_t)8 * i * Nw);
        asm volatile("cp.async.commit_group;\n");
    }

    for (int kt = 0; kt < nkt; ++kt) {
        asm volatile("cp.async.wait_group 0;\n");
        __syncthreads();

        if (kt + 1 < nkt) {
            const int nb = (kt + 1) & 1;
            const float* Ag = A + (m0 + arow) * K + (kt + 1) * 32 + acol;
#pragma unroll
            for (int i = 0; i < 4; i++)
                cp_async16(&sAb[nb][(arow + 32 * i) * AS_STRIDE + acol],
                           Ag + (size_t)32 * i * K);
            const float* Wg = W + (size_t)((kt + 1) * 32 + brow) * Nw + n0 + bcol;
#pragma unroll
            for (int i = 0; i < 4; i++)
                cp_async16(&sBb[nb][(brow + 8 * i) * BS_STRIDE + bcol],
                           Wg + (size_t)8 * i * Nw);
            asm volatile("cp.async.commit_group;\n");
        }

        const float* As = sAb[kt & 1];
        const float* Bs = sBb[kt & 1];

#pragma unroll
        for (int ks = 0; ks < 4; ++ks) {
            const int ck = ks * 8;
            unsigned bh[4][2], br[4][2];
#pragma unroll
            for (int nt = 0; nt < 4; nt++) {
                const int c0 = wn * 32 + nt * 8 + g;
                const float* p = Bs + (ck + t) * BS_STRIDE + c0;
                tf32_split(p[0],             bh[nt][0], br[nt][0]);
                tf32_split(p[4 * BS_STRIDE], bh[nt][1], br[nt][1]);
            }
#pragma unroll
            for (int mt = 0; mt < 4; mt++) {
                const int r0 = wm * 64 + mt * 16 + g;
                const float* p = As + r0 * AS_STRIDE + ck + t;
                unsigned ah[4], ar[4];
                tf32_split(p[0],                 ah[0], ar[0]);
                tf32_split(p[8 * AS_STRIDE],     ah[1], ar[1]);
                tf32_split(p[4],                 ah[2], ar[2]);
                tf32_split(p[8 * AS_STRIDE + 4], ah[3], ar[3]);
#pragma unroll
                for (int nt = 0; nt < 4; nt++) {
                    mma_tf32(acc[mt][nt], ar, bh[nt]);
                    mma_tf32(acc[mt][nt], ah, br[nt]);
                    mma_tf32(acc[mt][nt], ah, bh[nt]);
                }
            }
        }
        __syncthreads();
    }

#pragma unroll
    for (int mt = 0; mt < 4; mt++) {
        const size_t r0 = m0 + wm * 64 + mt * 16 + g;
#pragma unroll
        for (int nt = 0; nt < 4; nt++) {
            const int col = n0 + wn * 32 + nt * 8 + 2 * t;
            const float b0 = bias[col], b1 = bias[col + 1];
            float* cp0 = C + r0 * ldc + col;
            float* cp1 = C + (r0 + 8) * ldc + col;
            *(float2*)cp0 = make_float2(acc[mt][nt][0] + b0, acc[mt][nt][1] + b1);
            *(float2*)cp1 = make_float2(acc[mt][nt][2] + b0, acc[mt][nt][3] + b1);
        }
    }
}

// ---------------------------------------------------------------------------
// Tensor-core attention: block = window, warp = head, fully warp-local.
// Per-warp smem: Q[64x32]@stride36 | K[64x32]@stride36 | V[64x32]@stride40;
// after QK^T, P[64x64]@stride68 aliases the Q+K region.
// QK^T and P·V in 3xTF32 mma; softmax in registers.
// ---------------------------------------------------------------------------
#define QS_STRIDE 36
#define KS_STRIDE 36
#define VS_STRIDE 40
#define PS_STRIDE 68
#define WARP_FLOATS (64 * QS_STRIDE + 64 * KS_STRIDE + 64 * VS_STRIDE)  // 7168
#define ATTN_SMEM (8 * WARP_FLOATS * 4)   // 229376 bytes

__global__ __launch_bounds__(256, 1)
void attn_tc(const float* __restrict__ qkv,
             const float* __restrict__ bias,   // g_bias [8][64][64]
             float* __restrict__ ao)
{
    extern __shared__ float sm[];
    const int b    = blockIdx.x;
    const int warp = threadIdx.x >> 5;        // = head h
    const int lane = threadIdx.x & 31;
    const int g = lane >> 2, t = lane & 3;
    const int h = warp;

    float* QS = sm + warp * WARP_FLOATS;
    float* KS = QS + 64 * QS_STRIDE;
    float* VS = KS + 64 * KS_STRIDE;
    float* PS = QS;                           // aliases Q+K (4352 <= 4608)

    // ---- load Q (scaled), K, V head slices ----
    const size_t base = (size_t)b * N_TOK * QKV_LD + h * HDIM;
#pragma unroll
    for (int i = lane; i < 512; i += 32) {
        const int row = i >> 3;
        const int c4  = (i & 7) << 2;
        const float* rp = qkv + base + (size_t)row * QKV_LD + c4;
        float4 q = *(const float4*)(rp);
        float4 k = *(const float4*)(rp + 256);
        float4 v = *(const float4*)(rp + 512);
        q.x *= SCALE_F; q.y *= SCALE_F; q.z *= SCALE_F; q.w *= SCALE_F;
        *(float4*)&QS[row * QS_STRIDE + c4] = q;
        *(float4*)&KS[row * KS_STRIDE + c4] = k;
        *(float4*)&VS[row * VS_STRIDE + c4] = v;
    }
    __syncwarp();

    // ---- S = Q @ K^T (3xTF32), accum 4(mt) x 8(nt) x 4 regs ----
    float s[4][8][4];
#pragma unroll
    for (int mt = 0; mt < 4; mt++)
#pragma unroll
        for (int nt = 0; nt < 8; nt++)
#pragma unroll
            for (int r = 0; r < 4; r++) s[mt][nt][r] = 0.0f;

#pragma unroll
    for (int ks = 0; ks < 4; ++ks) {
        const int ck = ks * 8;
        unsigned ah[4][4], ar[4][4];
#pragma unroll
        for (int mt = 0; mt < 4; mt++) {
            const float* p = QS + (mt * 16 + g) * QS_STRIDE + ck + t;
            tf32_split(p[0],                 ah[mt][0], ar[mt][0]);
            tf32_split(p[8 * QS_STRIDE],     ah[mt][1], ar[mt][1]);
            tf32_split(p[4],                 ah[mt][2], ar[mt][2]);
            tf32_split(p[8 * QS_STRIDE + 4], ah[mt][3], ar[mt][3]);
        }
#pragma unroll
        for (int nt = 0; nt < 8; nt++) {
            // B-frag: element (kd, m) = K[m][kd]
            const float* p = KS + (nt * 8 + g) * KS_STRIDE + ck + t;
            unsigned bh[2], br[2];
            tf32_split(p[0],              bh[0], br[0]);   // (ck+t,   n=nt*8+g)
            tf32_split(p[4],              bh[1], br[1]);   // (ck+t+4, n)
#pragma unroll
            for (int mt = 0; mt < 4; mt++) {
                mma_tf32(s[mt][nt], ar[mt], bh);
                mma_tf32(s[mt][nt], ah[mt], br);
                mma_tf32(s[mt][nt], ah[mt], bh);
            }
        }
    }

    // ---- add rel-pos bias (L2-resident table) ----
    const float* bh_tab = bias + h * (N_TOK * N_TOK);
#pragma unroll
    for (int mt = 0; mt < 4; mt++) {
        const int r0 = mt * 16 + g;
#pragma unroll
        for (int nt = 0; nt < 8; nt++) {
            const int c = nt * 8 + 2 * t;
            float2 b0 = *(const float2*)&bh_tab[r0 * 64 + c];
            float2 b1 = *(const float2*)&bh_tab[(r0 + 8) * 64 + c];
            s[mt][nt][0] += b0.x;  s[mt][nt][1] += b0.y;
            s[mt][nt][2] += b1.x;  s[mt][nt][3] += b1.y;
        }
    }

    // ---- softmax over each row (64 cols spread across 8 nt x 4 t-lanes) ----
#pragma unroll
    for (int mt = 0; mt < 4; mt++) {
        float m0 = -1e30f, m1 = -1e30f;
#pragma unroll
        for (int nt = 0; nt < 8; nt++) {
            m0 = fmaxf(m0, fmaxf(s[mt][nt][0], s[mt][nt][1]));
            m1 = fmaxf(m1, fmaxf(s[mt][nt][2], s[mt][nt][3]));
        }
        m0 = fmaxf(m0, __shfl_xor_sync(0xffffffffu, m0, 1));
        m0 = fmaxf(m0, __shfl_xor_sync(0xffffffffu, m0, 2));
        m1 = fmaxf(m1, __shfl_xor_sync(0xffffffffu, m1, 1));
        m1 = fmaxf(m1, __shfl_xor_sync(0xffffffffu, m1, 2));
        float s0 = 0.0f, s1 = 0.0f;
#pragma unroll
        for (int nt = 0; nt < 8; nt++) {
            s[mt][nt][0] = __expf(s[mt][nt][0] - m0);
            s[mt][nt][1] = __expf(s[mt][nt][1] - m0);
            s[mt][nt][2] = __expf(s[mt][nt][2] - m1);
            s[mt][nt][3] = __expf(s[mt][nt][3] - m1);
            s0 += s[mt][nt][0] + s[mt][nt][1];
            s1 += s[mt][nt][2] + s[mt][nt][3];
        }
        s0 += __shfl_xor_sync(0xffffffffu, s0, 1);
        s0 += __shfl_xor_sync(0xffffffffu, s0, 2);
        s1 += __shfl_xor_sync(0xffffffffu, s1, 1);
        s1 += __shfl_xor_sync(0xffffffffu, s1, 2);
        const float i0 = __frcp_rn(s0), i1 = __frcp_rn(s1);
#pragma unroll
        for (int nt = 0; nt < 8; nt++) {
            s[mt][nt][0] *= i0;  s[mt][nt][1] *= i0;
            s[mt][nt][2] *= i1;  s[mt][nt][3] *= i1;
        }
    }
    __syncwarp();   // Q/K reads done by all lanes before P overwrites region

    // ---- write P to smem (stride 68; banks 4g+2t -> minor 2-way on store) ----
#pragma unroll
    for (int mt = 0; mt < 4; mt++) {
        const int r0 = mt * 16 + g;
#pragma unroll
        for (int nt = 0; nt < 8; nt++) {
            const int c = nt * 8 + 2 * t;
            *(float2*)&PS[r0 * PS_STRIDE + c]       = make_float2(s[mt][nt][0], s[mt][nt][1]);
            *(float2*)&PS[(r0 + 8) * PS_STRIDE + c] = make_float2(s[mt][nt][2], s[mt][nt][3]);
        }
    }
    __syncwarp();

    // ---- O = P @ V (3xTF32): M=64, N=32, K=64 ----
    float o[4][4][4];
#pragma unroll
    for (int mt = 0; mt < 4; mt++)
#pragma unroll
        for (int nt = 0; nt < 4; nt++)
#pragma unroll
            for (int r = 0; r < 4; r++) o[mt][nt][r] = 0.0f;

#pragma unroll
    for (int ks = 0; ks < 8; ++ks) {
        const int ck = ks * 8;
        unsigned ah[4][4], ar[4][4];
#pragma unroll
        for (int mt = 0; mt < 4; mt++) {
            const float* p = PS + (mt * 16 + g) * PS_STRIDE + ck + t;
            tf32_split(p[0],                 ah[mt][0], ar[mt][0]);
            tf32_split(p[8 * PS_STRIDE],     ah[mt][1], ar[mt][1]);
            tf32_split(p[4],                 ah[mt][2], ar[mt][2]);
            tf32_split(p[8 * PS_STRIDE + 4], ah[mt][3], ar[mt][3]);
        }
#pragma unroll
        for (int nt = 0; nt < 4; nt++) {
            // B-frag: element (kd=token, n=dim) = V[token][dim]
            const float* p = VS + (ck + t) * VS_STRIDE + nt * 8 + g;
            unsigned bh[2], br[2];
            tf32_split(p[0],               bh[0], br[0]);
            tf32_split(p[4 * VS_STRIDE],   bh[1], br[1]);
#pragma unroll
            for (int mt = 0; mt < 4; mt++) {
                mma_tf32(o[mt][nt], ar[mt], bh);
                mma_tf32(o[mt][nt], ah[mt], br);
                mma_tf32(o[mt][nt], ah[mt], bh);
            }
        }
    }

    // ---- store O ----
#pragma unroll
    for (int mt = 0; mt < 4; mt++) {
        const int r0 = mt * 16 + g;
#pragma unroll
        for (int nt = 0; nt < 4; nt++) {
            const int col = h * HDIM + nt * 8 + 2 * t;
            float* op0 = ao + ((size_t)b * N_TOK + r0)     * DIM_C + col;
            float* op1 = ao + ((size_t)b * N_TOK + r0 + 8) * DIM_C + col;
            *(float2*)op0 = make_float2(o[mt][nt][0], o[mt][nt][1]);
            *(float2*)op1 = make_float2(o[mt][nt][2], o[mt][nt][3]);
        }
    }
}

// ---------------------------------------------------------------------------
extern "C" void kernel_launch(void* const* d_in, const int* in_sizes, int n_in,
                              void* d_out, int out_size)
{
    const float* x      = (const float*)d_in[0];
    const float* wq     = (const float*)d_in[1];
    const float* bq     = (const float*)d_in[2];
    const float* wkv    = (const float*)d_in[3];
    const float* bkv    = (const float*)d_in[4];
    const float* wp     = (const float*)d_in[5];
    const float* bp     = (const float*)d_in[6];
    const float* rpb    = (const float*)d_in[7];
    const int*   relidx = (const int*)  d_in[8];
    float* out = (float*)d_out;

    float *qkv = nullptr, *ao = nullptr, *wqkv = nullptr, *bqkv = nullptr, *bias = nullptr;
    cudaGetSymbolAddress((void**)&qkv,  g_qkv);
    cudaGetSymbolAddress((void**)&ao,   g_ao);
    cudaGetSymbolAddress((void**)&wqkv, g_wqkv);
    cudaGetSymbolAddress((void**)&bqkv, g_bqkv);
    cudaGetSymbolAddress((void**)&bias, g_bias);

    cudaFuncSetAttribute(gemm_tf32, cudaFuncAttributeMaxDynamicSharedMemorySize, GEMM_SMEM);
    cudaFuncSetAttribute(attn_tc,   cudaFuncAttributeMaxDynamicSharedMemorySize, ATTN_SMEM);

    // 0) pack weights + bias table
    pack_w<<<(DIM_C * QKV_LD + 255) / 256, 256>>>(wq, bq, wkv, bkv, rpb, relidx);

    // 1) qkv = x @ wqkv + bqkv
    {
        dim3 grid(M_ROWS / 128, QKV_LD / 128);
        gemm_tf32<<<grid, 256, GEMM_SMEM>>>(x, wqkv, bqkv, qkv, DIM_C, QKV_LD, QKV_LD);
    }
    // 2) attention
    attn_tc<<<B_WIN, 256, ATTN_SMEM>>>(qkv, bias, ao);

    // 3) out = ao @ wp + bp
    {
        dim3 grid(M_ROWS / 128, DIM_C / 128);
        gemm_tf32<<<grid, 256, GEMM_SMEM>>>(ao, wp, bp, out, DIM_C, DIM_C, DIM_C);
    }
}

// round 5
// speedup vs baseline: 2.0610x; 1.2375x over previous
#include <cuda_runtime.h>
#include <cuda_bf16.h>
#include <cstdint>

// ---------------------------------------------------------------------------
// TotalAttention (Swin window attention), 3xBF16 pipeline:
//   0a) split_x: x (fp32) -> xhi/xres bf16 planes [M][256] (k-major)
//   0b) pack_w: wq|wkv -> transposed split planes [768][256]; wp -> [256][256];
//       biases; bias table g_bias[h][n][m]
//   1) 3xBF16 MMA GEMM: qkv = x @ wqkv + bqkv      -> g_qkv fp32 [M x 768]
//   2) tensor-core attention (warp = head, 3xTF32) -> ao hi/res bf16 planes
//   3) 3xBF16 MMA GEMM: out = ao @ wp + bp         -> d_out fp32
// 3xBF16: f = hi + res (both bf16-rn); acc += ah*bh + ah*br + ar*bh.
// ---------------------------------------------------------------------------

#define B_WIN   4096
#define N_TOK   64
#define DIM_C   256
#define HEADS   8
#define HDIM    32
#define M_ROWS  (B_WIN * N_TOK)        // 262144
#define QKV_LD  768
#define SCALE_F 0.17677669529663687f   // 32^-0.5

__device__ float g_qkv[(size_t)M_ROWS * QKV_LD];            // 805 MB fp32
__device__ unsigned short g_xhi [(size_t)M_ROWS * DIM_C];   // bf16 planes
__device__ unsigned short g_xres[(size_t)M_ROWS * DIM_C];
__device__ unsigned short g_aohi [(size_t)M_ROWS * DIM_C];
__device__ unsigned short g_aores[(size_t)M_ROWS * DIM_C];
__device__ unsigned short g_wthi [QKV_LD * DIM_C];          // wqkv^T [768][256]
__device__ unsigned short g_wtres[QKV_LD * DIM_C];
__device__ unsigned short g_wpthi [DIM_C * DIM_C];          // wp^T [256][256]
__device__ unsigned short g_wptres[DIM_C * DIM_C];
__device__ float g_bqkv[QKV_LD];
__device__ float g_bias[HEADS * N_TOK * N_TOK];             // [h][n][m]

// ---------------------------------------------------------------------------
__device__ __forceinline__ void cp_async16(void* smem_dst, const void* gsrc) {
    unsigned saddr = (unsigned)__cvta_generic_to_shared(smem_dst);
    asm volatile("cp.async.cg.shared.global [%0], [%1], 16;\n"
                 :: "r"(saddr), "l"(gsrc));
}

__device__ __forceinline__ void mma_bf16(float* c, const unsigned* a, const unsigned* b) {
    asm volatile(
        "mma.sync.aligned.m16n8k16.row.col.f32.bf16.bf16.f32 "
        "{%0,%1,%2,%3}, {%4,%5,%6,%7}, {%8,%9}, {%0,%1,%2,%3};\n"
        : "+f"(c[0]), "+f"(c[1]), "+f"(c[2]), "+f"(c[3])
        : "r"(a[0]), "r"(a[1]), "r"(a[2]), "r"(a[3]),
          "r"(b[0]), "r"(b[1]));
}

__device__ __forceinline__ void mma_tf32(float* c, const unsigned* a, const unsigned* b) {
    asm volatile(
        "mma.sync.aligned.m16n8k8.row.col.f32.tf32.tf32.f32 "
        "{%0,%1,%2,%3}, {%4,%5,%6,%7}, {%8,%9}, {%0,%1,%2,%3};\n"
        : "+f"(c[0]), "+f"(c[1]), "+f"(c[2]), "+f"(c[3])
        : "r"(a[0]), "r"(a[1]), "r"(a[2]), "r"(a[3]),
          "r"(b[0]), "r"(b[1]));
}

__device__ __forceinline__ void tf32_split(float f, unsigned& hi, unsigned& res) {
    hi  = __float_as_uint(f) & 0xFFFFE000u;
    res = __float_as_uint(f - __uint_as_float(hi));
}

// split scalar f -> (hi, res) bf16
__device__ __forceinline__ void bf16_split(float f, unsigned short& hi, unsigned short& res) {
    __nv_bfloat16 h = __float2bfloat16_rn(f);
    float r = f - __bfloat162float(h);
    hi  = __bfloat16_as_ushort(h);
    res = __bfloat16_as_ushort(__float2bfloat16_rn(r));
}

// split pair (a,b) -> packed bf16x2 hi/res words
__device__ __forceinline__ void bf16_split_pack(float a, float b, unsigned& hi, unsigned& res) {
    unsigned short ha, ra, hb, rb;
    bf16_split(a, ha, ra);
    bf16_split(b, hb, rb);
    hi  = (unsigned)ha | ((unsigned)hb << 16);
    res = (unsigned)ra | ((unsigned)rb << 16);
}

// ---------------------------------------------------------------------------
// split_x: x fp32 -> bf16 hi/res planes (one float2 per thread)
// ---------------------------------------------------------------------------
__global__ __launch_bounds__(256)
void split_x(const float* __restrict__ x)
{
    size_t idx = (size_t)blockIdx.x * blockDim.x + threadIdx.x;
    if (idx < (size_t)M_ROWS * DIM_C / 2) {
        float2 v = ((const float2*)x)[idx];
        unsigned hi, res;
        bf16_split_pack(v.x, v.y, hi, res);
        ((unsigned*)g_xhi)[idx]  = hi;
        ((unsigned*)g_xres)[idx] = res;
    }
}

// ---------------------------------------------------------------------------
// pack_w: transposed split weight planes + biases + bias table
// ---------------------------------------------------------------------------
__global__ void pack_w(const float* __restrict__ wq, const float* __restrict__ bq,
                       const float* __restrict__ wkv, const float* __restrict__ bkv,
                       const float* __restrict__ wp,
                       const float* __restrict__ rpb, const int* __restrict__ relidx)
{
    int i = blockIdx.x * blockDim.x + threadIdx.x;
    if (i < QKV_LD * DIM_C) {                 // wqkv^T: [n=768][k=256]
        int n = i / DIM_C, k = i % DIM_C;
        float v = (n < DIM_C) ? wq[k * DIM_C + n] : wkv[k * 512 + (n - DIM_C)];
        bf16_split(v, g_wthi[i], g_wtres[i]);
    }
    if (i < DIM_C * DIM_C) {                  // wp^T: [n=256][k=256]
        int n = i / DIM_C, k = i % DIM_C;
        bf16_split(wp[k * DIM_C + n], g_wpthi[i], g_wptres[i]);
    }
    if (i < QKV_LD) g_bqkv[i] = (i < DIM_C) ? bq[i] : bkv[i - DIM_C];
    if (i < HEADS * N_TOK * N_TOK) {
        int h = i >> 12, nm = i & 4095;
        g_bias[i] = rpb[relidx[nm] * HEADS + h];
    }
}

// ---------------------------------------------------------------------------
// 3xBF16 tensor-core GEMM: C[m,n] = A[m,:K] @ B[n,:K]^T + bias[n]
// A planes [M][K], B planes [N][K], both k-major bf16 hi/res.
// BM=128, BN=128, BK=32; 256 thr = 8 warps (2x4), warp tile 64x32;
// mma m16n8k16 (2 k-steps per tile). Smem row stride 40 bf16 (80 B):
// fragment loads touch 32 distinct banks (bank = (row*20 + ck/2 + t [+4]) mod 32).
// Requires M%128==0, N%128==0, K%32==0.
// ---------------------------------------------------------------------------
#define TPAD 40
#define TE (128 * TPAD)                 // elems per tile plane
#define BUF_ELEMS (4 * TE)              // Ahi,Ares,Bhi,Bres
#define GEMM_SMEM (2 * BUF_ELEMS * 2)   // bytes = 81920

__global__ __launch_bounds__(256, 2)
void gemm_bf16x3(const unsigned short* __restrict__ Ahi,
                 const unsigned short* __restrict__ Ares,
                 const unsigned short* __restrict__ Bhi,
                 const unsigned short* __restrict__ Bres,
                 const float* __restrict__ bias, float* __restrict__ C,
                 int K, int ldc)
{
    extern __shared__ __align__(16) unsigned short smu[];

    const int tid  = threadIdx.x;
    const int warp = tid >> 5, lane = tid & 31;
    const int wm = warp >> 2, wn = warp & 3;
    const int g  = lane >> 2, t  = lane & 3;
    const size_t m0 = (size_t)blockIdx.x * 128;
    const size_t n0 = (size_t)blockIdx.y * 128;

    // cp.async mapping: 512 16B-chunks per tile plane; 2 per thread per plane
    const int c0   = tid * 2;
    const int row0 = c0 >> 2, cc0 = (c0 & 3) * 8;
    const int row1 = (c0 + 1) >> 2, cc1 = ((c0 + 1) & 3) * 8;

    const int nkt = K / 32;

    float acc[4][4][4];
#pragma unroll
    for (int mt = 0; mt < 4; mt++)
#pragma unroll
        for (int nt = 0; nt < 4; nt++)
#pragma unroll
            for (int r = 0; r < 4; r++) acc[mt][nt][r] = 0.0f;

    // prologue: fill buffer 0
    {
        unsigned short* s = smu;
        cp_async16(&s[0 * TE + row0 * TPAD + cc0], Ahi  + (m0 + row0) * K + cc0);
        cp_async16(&s[0 * TE + row1 * TPAD + cc1], Ahi  + (m0 + row1) * K + cc1);
        cp_async16(&s[1 * TE + row0 * TPAD + cc0], Ares + (m0 + row0) * K + cc0);
        cp_async16(&s[1 * TE + row1 * TPAD + cc1], Ares + (m0 + row1) * K + cc1);
        cp_async16(&s[2 * TE + row0 * TPAD + cc0], Bhi  + (n0 + row0) * K + cc0);
        cp_async16(&s[2 * TE + row1 * TPAD + cc1], Bhi  + (n0 + row1) * K + cc1);
        cp_async16(&s[3 * TE + row0 * TPAD + cc0], Bres + (n0 + row0) * K + cc0);
        cp_async16(&s[3 * TE + row1 * TPAD + cc1], Bres + (n0 + row1) * K + cc1);
        asm volatile("cp.async.commit_group;\n");
    }

    for (int kt = 0; kt < nkt; ++kt) {
        asm volatile("cp.async.wait_group 0;\n");
        __syncthreads();

        if (kt + 1 < nkt) {
            unsigned short* s = smu + ((kt + 1) & 1) * BUF_ELEMS;
            const int ko = (kt + 1) * 32;
            cp_async16(&s[0 * TE + row0 * TPAD + cc0], Ahi  + (m0 + row0) * K + ko + cc0);
            cp_async16(&s[0 * TE + row1 * TPAD + cc1], Ahi  + (m0 + row1) * K + ko + cc1);
            cp_async16(&s[1 * TE + row0 * TPAD + cc0], Ares + (m0 + row0) * K + ko + cc0);
            cp_async16(&s[1 * TE + row1 * TPAD + cc1], Ares + (m0 + row1) * K + ko + cc1);
            cp_async16(&s[2 * TE + row0 * TPAD + cc0], Bhi  + (n0 + row0) * K + ko + cc0);
            cp_async16(&s[2 * TE + row1 * TPAD + cc1], Bhi  + (n0 + row1) * K + ko + cc1);
            cp_async16(&s[3 * TE + row0 * TPAD + cc0], Bres + (n0 + row0) * K + ko + cc0);
            cp_async16(&s[3 * TE + row1 * TPAD + cc1], Bres + (n0 + row1) * K + ko + cc1);
            asm volatile("cp.async.commit_group;\n");
        }

        const unsigned short* sb = smu + (kt & 1) * BUF_ELEMS;
        const unsigned short* As_hi  = sb + 0 * TE;
        const unsigned short* As_res = sb + 1 * TE;
        const unsigned short* Bs_hi  = sb + 2 * TE;
        const unsigned short* Bs_res = sb + 3 * TE;

#pragma unroll
        for (int ks = 0; ks < 2; ++ks) {
            const int ck = ks * 16;
            unsigned bh[4][2], br[4][2];
#pragma unroll
            for (int nt = 0; nt < 4; nt++) {
                const int np = wn * 32 + nt * 8 + g;
                const unsigned short* ph = Bs_hi  + np * TPAD + ck + 2 * t;
                const unsigned short* pr = Bs_res + np * TPAD + ck + 2 * t;
                bh[nt][0] = *(const unsigned*)ph;        // k = ck+2t, ck+2t+1
                bh[nt][1] = *(const unsigned*)(ph + 8);  // k = ck+2t+8, +9
                br[nt][0] = *(const unsigned*)pr;
                br[nt][1] = *(const unsigned*)(pr + 8);
            }
#pragma unroll
            for (int mt = 0; mt < 4; mt++) {
                const int r0 = wm * 64 + mt * 16 + g;
                const unsigned short* ph = As_hi  + r0 * TPAD + ck + 2 * t;
                const unsigned short* pr = As_res + r0 * TPAD + ck + 2 * t;
                unsigned ah[4], ar[4];
                ah[0] = *(const unsigned*)ph;                  // (g,   k..k+1)
                ah[1] = *(const unsigned*)(ph + 8 * TPAD);     // (g+8, k..k+1)
                ah[2] = *(const unsigned*)(ph + 8);            // (g,   k+8..k+9)
                ah[3] = *(const unsigned*)(ph + 8 * TPAD + 8); // (g+8, k+8..k+9)
                ar[0] = *(const unsigned*)pr;
                ar[1] = *(const unsigned*)(pr + 8 * TPAD);
                ar[2] = *(const unsigned*)(pr + 8);
                ar[3] = *(const unsigned*)(pr + 8 * TPAD + 8);
#pragma unroll
                for (int nt = 0; nt < 4; nt++) {
                    mma_bf16(acc[mt][nt], ar, bh[nt]);
                    mma_bf16(acc[mt][nt], ah, br[nt]);
                    mma_bf16(acc[mt][nt], ah, bh[nt]);
                }
            }
        }
        __syncthreads();
    }

    // epilogue: c0/c1 -> (g, 2t..2t+1), c2/c3 -> (g+8, 2t..2t+1)
#pragma unroll
    for (int mt = 0; mt < 4; mt++) {
        const size_t r0 = m0 + wm * 64 + mt * 16 + g;
#pragma unroll
        for (int nt = 0; nt < 4; nt++) {
            const size_t col = n0 + wn * 32 + nt * 8 + 2 * t;
            const float b0 = bias[col], b1 = bias[col + 1];
            float* cp0 = C + r0 * ldc + col;
            float* cp1 = C + (r0 + 8) * ldc + col;
            *(float2*)cp0 = make_float2(acc[mt][nt][0] + b0, acc[mt][nt][1] + b1);
            *(float2*)cp1 = make_float2(acc[mt][nt][2] + b0, acc[mt][nt][3] + b1);
        }
    }
}

// ---------------------------------------------------------------------------
// Tensor-core attention: block = window, warp = head (3xTF32, as round 4).
// Epilogue now writes ao as bf16 hi/res planes for the out-proj GEMM.
// ---------------------------------------------------------------------------
#define QS_STRIDE 36
#define KS_STRIDE 36
#define VS_STRIDE 40
#define PS_STRIDE 68
#define WARP_FLOATS (64 * QS_STRIDE + 64 * KS_STRIDE + 64 * VS_STRIDE)  // 7168
#define ATTN_SMEM (8 * WARP_FLOATS * 4)   // 229376 bytes

__global__ __launch_bounds__(256, 1)
void attn_tc(const float* __restrict__ qkv,
             const float* __restrict__ bias)
{
    extern __shared__ float sm[];
    const int b    = blockIdx.x;
    const int warp = threadIdx.x >> 5;        // = head h
    const int lane = threadIdx.x & 31;
    const int g = lane >> 2, t = lane & 3;
    const int h = warp;

    float* QS = sm + warp * WARP_FLOATS;
    float* KS = QS + 64 * QS_STRIDE;
    float* VS = KS + 64 * KS_STRIDE;
    float* PS = QS;                           // aliases Q+K

    const size_t base = (size_t)b * N_TOK * QKV_LD + h * HDIM;
#pragma unroll
    for (int i = lane; i < 512; i += 32) {
        const int row = i >> 3;
        const int c4  = (i & 7) << 2;
        const float* rp = qkv + base + (size_t)row * QKV_LD + c4;
        float4 q = *(const float4*)(rp);
        float4 k = *(const float4*)(rp + 256);
        float4 v = *(const float4*)(rp + 512);
        q.x *= SCALE_F; q.y *= SCALE_F; q.z *= SCALE_F; q.w *= SCALE_F;
        *(float4*)&QS[row * QS_STRIDE + c4] = q;
        *(float4*)&KS[row * KS_STRIDE + c4] = k;
        *(float4*)&VS[row * VS_STRIDE + c4] = v;
    }
    __syncwarp();

    // S = Q @ K^T
    float s[4][8][4];
#pragma unroll
    for (int mt = 0; mt < 4; mt++)
#pragma unroll
        for (int nt = 0; nt < 8; nt++)
#pragma unroll
            for (int r = 0; r < 4; r++) s[mt][nt][r] = 0.0f;

#pragma unroll
    for (int ks = 0; ks < 4; ++ks) {
        const int ck = ks * 8;
        unsigned ah[4][4], ar[4][4];
#pragma unroll
        for (int mt = 0; mt < 4; mt++) {
            const float* p = QS + (mt * 16 + g) * QS_STRIDE + ck + t;
            tf32_split(p[0],                 ah[mt][0], ar[mt][0]);
            tf32_split(p[8 * QS_STRIDE],     ah[mt][1], ar[mt][1]);
            tf32_split(p[4],                 ah[mt][2], ar[mt][2]);
            tf32_split(p[8 * QS_STRIDE + 4], ah[mt][3], ar[mt][3]);
        }
#pragma unroll
        for (int nt = 0; nt < 8; nt++) {
            const float* p = KS + (nt * 8 + g) * KS_STRIDE + ck + t;
            unsigned bh[2], br[2];
            tf32_split(p[0], bh[0], br[0]);
            tf32_split(p[4], bh[1], br[1]);
#pragma unroll
            for (int mt = 0; mt < 4; mt++) {
                mma_tf32(s[mt][nt], ar[mt], bh);
                mma_tf32(s[mt][nt], ah[mt], br);
                mma_tf32(s[mt][nt], ah[mt], bh);
            }
        }
    }

    // bias
    const float* bh_tab = bias + h * (N_TOK * N_TOK);
#pragma unroll
    for (int mt = 0; mt < 4; mt++) {
        const int r0 = mt * 16 + g;
#pragma unroll
        for (int nt = 0; nt < 8; nt++) {
            const int c = nt * 8 + 2 * t;
            float2 b0 = *(const float2*)&bh_tab[r0 * 64 + c];
            float2 b1 = *(const float2*)&bh_tab[(r0 + 8) * 64 + c];
            s[mt][nt][0] += b0.x;  s[mt][nt][1] += b0.y;
            s[mt][nt][2] += b1.x;  s[mt][nt][3] += b1.y;
        }
    }

    // softmax
#pragma unroll
    for (int mt = 0; mt < 4; mt++) {
        float m0 = -1e30f, m1 = -1e30f;
#pragma unroll
        for (int nt = 0; nt < 8; nt++) {
            m0 = fmaxf(m0, fmaxf(s[mt][nt][0], s[mt][nt][1]));
            m1 = fmaxf(m1, fmaxf(s[mt][nt][2], s[mt][nt][3]));
        }
        m0 = fmaxf(m0, __shfl_xor_sync(0xffffffffu, m0, 1));
        m0 = fmaxf(m0, __shfl_xor_sync(0xffffffffu, m0, 2));
        m1 = fmaxf(m1, __shfl_xor_sync(0xffffffffu, m1, 1));
        m1 = fmaxf(m1, __shfl_xor_sync(0xffffffffu, m1, 2));
        float s0 = 0.0f, s1 = 0.0f;
#pragma unroll
        for (int nt = 0; nt < 8; nt++) {
            s[mt][nt][0] = __expf(s[mt][nt][0] - m0);
            s[mt][nt][1] = __expf(s[mt][nt][1] - m0);
            s[mt][nt][2] = __expf(s[mt][nt][2] - m1);
            s[mt][nt][3] = __expf(s[mt][nt][3] - m1);
            s0 += s[mt][nt][0] + s[mt][nt][1];
            s1 += s[mt][nt][2] + s[mt][nt][3];
        }
        s0 += __shfl_xor_sync(0xffffffffu, s0, 1);
        s0 += __shfl_xor_sync(0xffffffffu, s0, 2);
        s1 += __shfl_xor_sync(0xffffffffu, s1, 1);
        s1 += __shfl_xor_sync(0xffffffffu, s1, 2);
        const float i0 = __frcp_rn(s0), i1 = __frcp_rn(s1);
#pragma unroll
        for (int nt = 0; nt < 8; nt++) {
            s[mt][nt][0] *= i0;  s[mt][nt][1] *= i0;
            s[mt][nt][2] *= i1;  s[mt][nt][3] *= i1;
        }
    }
    __syncwarp();

    // P -> smem
#pragma unroll
    for (int mt = 0; mt < 4; mt++) {
        const int r0 = mt * 16 + g;
#pragma unroll
        for (int nt = 0; nt < 8; nt++) {
            const int c = nt * 8 + 2 * t;
            *(float2*)&PS[r0 * PS_STRIDE + c]       = make_float2(s[mt][nt][0], s[mt][nt][1]);
            *(float2*)&PS[(r0 + 8) * PS_STRIDE + c] = make_float2(s[mt][nt][2], s[mt][nt][3]);
        }
    }
    __syncwarp();

    // O = P @ V
    float o[4][4][4];
#pragma unroll
    for (int mt = 0; mt < 4; mt++)
#pragma unroll
        for (int nt = 0; nt < 4; nt++)
#pragma unroll
            for (int r = 0; r < 4; r++) o[mt][nt][r] = 0.0f;

#pragma unroll
    for (int ks = 0; ks < 8; ++ks) {
        const int ck = ks * 8;
        unsigned ah[4][4], ar[4][4];
#pragma unroll
        for (int mt = 0; mt < 4; mt++) {
            const float* p = PS + (mt * 16 + g) * PS_STRIDE + ck + t;
            tf32_split(p[0],                 ah[mt][0], ar[mt][0]);
            tf32_split(p[8 * PS_STRIDE],     ah[mt][1], ar[mt][1]);
            tf32_split(p[4],                 ah[mt][2], ar[mt][2]);
            tf32_split(p[8 * PS_STRIDE + 4], ah[mt][3], ar[mt][3]);
        }
#pragma unroll
        for (int nt = 0; nt < 4; nt++) {
            const float* p = VS + (ck + t) * VS_STRIDE + nt * 8 + g;
            unsigned bh[2], br[2];
            tf32_split(p[0],             bh[0], br[0]);
            tf32_split(p[4 * VS_STRIDE], bh[1], br[1]);
#pragma unroll
            for (int mt = 0; mt < 4; mt++) {
                mma_tf32(o[mt][nt], ar[mt], bh);
                mma_tf32(o[mt][nt], ah[mt], br);
                mma_tf32(o[mt][nt], ah[mt], bh);
            }
        }
    }

    // store O as bf16 hi/res planes
#pragma unroll
    for (int mt = 0; mt < 4; mt++) {
        const int r0 = mt * 16 + g;
#pragma unroll
        for (int nt = 0; nt < 4; nt++) {
            const int col = h * HDIM + nt * 8 + 2 * t;
            const size_t e0 = ((size_t)b * N_TOK + r0)     * DIM_C + col;
            const size_t e1 = ((size_t)b * N_TOK + r0 + 8) * DIM_C + col;
            unsigned hi, res;
            bf16_split_pack(o[mt][nt][0], o[mt][nt][1], hi, res);
            ((unsigned*)g_aohi)[e0 >> 1]  = hi;
            ((unsigned*)g_aores)[e0 >> 1] = res;
            bf16_split_pack(o[mt][nt][2], o[mt][nt][3], hi, res);
            ((unsigned*)g_aohi)[e1 >> 1]  = hi;
            ((unsigned*)g_aores)[e1 >> 1] = res;
        }
    }
}

// ---------------------------------------------------------------------------
extern "C" void kernel_launch(void* const* d_in, const int* in_sizes, int n_in,
                              void* d_out, int out_size)
{
    const float* x      = (const float*)d_in[0];
    const float* wq     = (const float*)d_in[1];
    const float* bq     = (const float*)d_in[2];
    const float* wkv    = (const float*)d_in[3];
    const float* bkv    = (const float*)d_in[4];
    const float* wp     = (const float*)d_in[5];
    const float* bp     = (const float*)d_in[6];
    const float* rpb    = (const float*)d_in[7];
    const int*   relidx = (const int*)  d_in[8];
    float* out = (float*)d_out;

    float *qkv = nullptr, *bqkv = nullptr, *bias = nullptr;
    unsigned short *xhi, *xres, *aohi, *aores, *wthi, *wtres, *wpthi, *wptres;
    cudaGetSymbolAddress((void**)&qkv,    g_qkv);
    cudaGetSymbolAddress((void**)&bqkv,   g_bqkv);
    cudaGetSymbolAddress((void**)&bias,   g_bias);
    cudaGetSymbolAddress((void**)&xhi,    g_xhi);
    cudaGetSymbolAddress((void**)&xres,   g_xres);
    cudaGetSymbolAddress((void**)&aohi,   g_aohi);
    cudaGetSymbolAddress((void**)&aores,  g_aores);
    cudaGetSymbolAddress((void**)&wthi,   g_wthi);
    cudaGetSymbolAddress((void**)&wtres,  g_wtres);
    cudaGetSymbolAddress((void**)&wpthi,  g_wpthi);
    cudaGetSymbolAddress((void**)&wptres, g_wptres);

    cudaFuncSetAttribute(gemm_bf16x3, cudaFuncAttributeMaxDynamicSharedMemorySize, GEMM_SMEM);
    cudaFuncSetAttribute(attn_tc,     cudaFuncAttributeMaxDynamicSharedMemorySize, ATTN_SMEM);

    // 0a) split x
    split_x<<<(M_ROWS * DIM_C / 2 + 255) / 256, 256>>>(x);
    // 0b) pack weights + bias table
    pack_w<<<(QKV_LD * DIM_C + 255) / 256, 256>>>(wq, bq, wkv, bkv, wp, rpb, relidx);

    // 1) qkv = x @ wqkv + bqkv (fp32 out)
    {
        dim3 grid(M_ROWS / 128, QKV_LD / 128);
        gemm_bf16x3<<<grid, 256, GEMM_SMEM>>>(xhi, xres, wthi, wtres, bqkv, qkv,
                                              DIM_C, QKV_LD);
    }
    // 2) attention (reads fp32 qkv, writes ao bf16 planes)
    attn_tc<<<B_WIN, 256, ATTN_SMEM>>>(qkv, bias);

    // 3) out = ao @ wp + bp
    {
        dim3 grid(M_ROWS / 128, DIM_C / 128);
        gemm_bf16x3<<<grid, 256, GEMM_SMEM>>>(aohi, aores, wpthi, wptres, bp, out,
                                              DIM_C, DIM_C);
    }
}